// round 1
// baseline (speedup 1.0000x reference)
#include <cuda_runtime.h>
#include <cooperative_groups.h>
#include <cooperative_groups/reduce.h>

namespace cg = cooperative_groups;

#define ALPHA_F 0.1f

constexpr int Bb  = 32;
constexpr int Tt  = 2048;
constexpr int DIN = 128;
constexpr int Hh  = 512;

// Scratch for x_proj = x @ I^T : [B*T, H] fp32 (128 MB)
__device__ float g_xproj[(size_t)Bb * Tt * Hh];

// ---------------- packed-f32x2 helpers (FFMA2 path, 2x fp32 rate) ----------
#define PACK2(d, lo, hi)   asm("mov.b64 %0, {%1, %2};" : "=l"(d) : "f"(lo), "f"(hi))
#define UNPACK2(lo, hi, s) asm("mov.b64 {%0, %1}, %2;" : "=f"(lo), "=f"(hi) : "l"(s))
#define FMA2(d, a, b)      asm("fma.rn.f32x2 %0, %1, %2, %0;" : "+l"(d) : "l"(a), "l"(b))

// =====================================================================
// Kernel 1: x_proj[m][h] = sum_d x[m][d] * I[h][d]   (NT GEMM, K=128)
// 128x128x32 tiles, 8x8 microtile per thread, FFMA2 inner product.
// =====================================================================
constexpr int BM = 128, BN = 128, BK = 32;

__global__ __launch_bounds__(256, 2) void proj_kernel(const float* __restrict__ X,
                                                      const float* __restrict__ Iw) {
    __shared__ float As[BK][BM + 4];
    __shared__ float Bs[BK][BN + 4];
    const int tid = threadIdx.x;
    const int tx  = tid & 15;   // N microtile index
    const int ty  = tid >> 4;   // M microtile index
    const long long m0 = (long long)blockIdx.y * BM;
    const int       n0 = blockIdx.x * BN;

    unsigned long long acc[8][4];
#pragma unroll
    for (int i = 0; i < 8; i++)
#pragma unroll
        for (int j = 0; j < 4; j++) acc[i][j] = 0ull;

    for (int kt = 0; kt < DIN; kt += BK) {
        // Cooperative load, stored K-major (transposed) into smem
#pragma unroll
        for (int q = 0; q < 4; q++) {
            int p   = tid + q * 256;   // 0..1023 float4 slots
            int row = p >> 3;          // 0..127
            int kq  = p & 7;           // 0..7 (k quad)
            float4 av = *(const float4*)(X + (m0 + row) * DIN + kt + kq * 4);
            As[kq * 4 + 0][row] = av.x; As[kq * 4 + 1][row] = av.y;
            As[kq * 4 + 2][row] = av.z; As[kq * 4 + 3][row] = av.w;
            float4 bv = *(const float4*)(Iw + (long long)(n0 + row) * DIN + kt + kq * 4);
            Bs[kq * 4 + 0][row] = bv.x; Bs[kq * 4 + 1][row] = bv.y;
            Bs[kq * 4 + 2][row] = bv.z; Bs[kq * 4 + 3][row] = bv.w;
        }
        __syncthreads();

#pragma unroll
        for (int k = 0; k < BK; k++) {
            float4 a0 = *(const float4*)&As[k][ty * 8];
            float4 a1 = *(const float4*)&As[k][ty * 8 + 4];
            const unsigned long long* bp =
                (const unsigned long long*)&Bs[k][tx * 8];
            unsigned long long pb0 = bp[0], pb1 = bp[1], pb2 = bp[2], pb3 = bp[3];
            float av[8] = {a0.x, a0.y, a0.z, a0.w, a1.x, a1.y, a1.z, a1.w};
#pragma unroll
            for (int i = 0; i < 8; i++) {
                unsigned long long pa;
                PACK2(pa, av[i], av[i]);
                FMA2(acc[i][0], pa, pb0);
                FMA2(acc[i][1], pa, pb1);
                FMA2(acc[i][2], pa, pb2);
                FMA2(acc[i][3], pa, pb3);
            }
        }
        __syncthreads();
    }

#pragma unroll
    for (int i = 0; i < 8; i++) {
        float4 o0, o1;
        UNPACK2(o0.x, o0.y, acc[i][0]);
        UNPACK2(o0.z, o0.w, acc[i][1]);
        UNPACK2(o1.x, o1.y, acc[i][2]);
        UNPACK2(o1.z, o1.w, acc[i][3]);
        long long row = m0 + ty * 8 + i;
        float* op = g_xproj + row * Hh + n0 + tx * 8;
        *(float4*)op       = o0;
        *(float4*)(op + 4) = o1;
    }
}

// =====================================================================
// Kernel 2: sequential scan. One block per batch, 128 threads, 4 h each.
// J = m n^T is rank-2: tanh(h) @ J^T = (tanh(h)@n) @ m^T -> per step only
// two scalars cross threads. Critical path: tanh -> redux -> bar -> update.
// =====================================================================
__device__ __forceinline__ float tanh_fast(float x) {
    float y;
    asm("tanh.approx.f32 %0, %1;" : "=f"(y) : "f"(x));
    return y;
}

__global__ __launch_bounds__(128, 1) void scan_kernel(const float* __restrict__ mw,
                                                      const float* __restrict__ nw,
                                                      float* __restrict__ out) {
    const int b    = blockIdx.x;
    const int tid  = threadIdx.x;
    const int wid  = tid >> 5;
    const int lane = tid & 31;

    __shared__ float4 wsum[2][2];  // [double buffer][8 floats: 4 warps x (s0,s1)]

    float h0v = 0.f, h1v = 0.f, h2v = 0.f, h3v = 0.f;
    const int i0 = tid * 4;
    float m0[4], m1[4], n0[4], n1[4];
#pragma unroll
    for (int j = 0; j < 4; j++) {
        m0[j] = mw[(i0 + j) * 2 + 0];
        m1[j] = mw[(i0 + j) * 2 + 1];
        n0[j] = nw[(i0 + j) * 2 + 0];
        n1[j] = nw[(i0 + j) * 2 + 1];
    }
    const float4* xp4  = (const float4*)(g_xproj + (size_t)b * Tt * Hh);
    float*        outb = out + (size_t)b * Tt * Hh;

    cg::thread_block blk = cg::this_thread_block();
    auto warp = cg::tiled_partition<32>(blk);

    float4 xp = xp4[tid];  // prefetched projection for step t
    for (int t = 0; t < Tt; t++) {
        // prefetch next step's projection (off critical path)
        float4 xpn = make_float4(0.f, 0.f, 0.f, 0.f);
        if (t + 1 < Tt) xpn = xp4[(size_t)(t + 1) * (Hh / 4) + tid];

        float th0 = tanh_fast(h0v), th1 = tanh_fast(h1v);
        float th2 = tanh_fast(h2v), th3 = tanh_fast(h3v);
        float s0 = th0 * n0[0] + th1 * n0[1] + th2 * n0[2] + th3 * n0[3];
        float s1 = th0 * n1[0] + th1 * n1[1] + th2 * n1[2] + th3 * n1[3];
        s0 = cg::reduce(warp, s0, cg::plus<float>());
        s1 = cg::reduce(warp, s1, cg::plus<float>());

        const int buf = t & 1;
        if (lane == 0) {
            float* w = (float*)&wsum[buf][0];
            w[wid * 2 + 0] = s0;
            w[wid * 2 + 1] = s1;
        }
        __syncthreads();
        float4 p0 = wsum[buf][0];
        float4 p1 = wsum[buf][1];
        float S0 = (p0.x + p0.z) + (p1.x + p1.z);
        float S1 = (p0.y + p0.w) + (p1.y + p1.w);

        h0v += ALPHA_F * (fmaf(m0[0], S0, fmaf(m1[0], S1, xp.x)) - h0v);
        h1v += ALPHA_F * (fmaf(m0[1], S0, fmaf(m1[1], S1, xp.y)) - h1v);
        h2v += ALPHA_F * (fmaf(m0[2], S0, fmaf(m1[2], S1, xp.z)) - h2v);
        h3v += ALPHA_F * (fmaf(m0[3], S0, fmaf(m1[3], S1, xp.w)) - h3v);

        *(float4*)&outb[(size_t)t * Hh + i0] = make_float4(h0v, h1v, h2v, h3v);
        xp = xpn;
    }
}

// =====================================================================
extern "C" void kernel_launch(void* const* d_in, const int* in_sizes, int n_in,
                              void* d_out, int out_size) {
    const float* x  = (const float*)d_in[0];  // [32, 2048, 128]
    const float* m  = (const float*)d_in[1];  // [512, 2]
    const float* n  = (const float*)d_in[2];  // [512, 2]
    const float* Iw = (const float*)d_in[3];  // [512, 128]
    float* out = (float*)d_out;               // [32, 2048, 512]

    dim3 pg(Hh / BN, (Bb * Tt) / BM);  // (4, 512)
    proj_kernel<<<pg, 256>>>(x, Iw);
    scan_kernel<<<Bb, 128>>>(m, n, out);
}

// round 3
// speedup vs baseline: 1.7233x; 1.7233x over previous
#include <cuda_runtime.h>

#define ALPHA_F 0.1f

constexpr int Bb  = 32;
constexpr int Tt  = 2048;
constexpr int DIN = 128;
constexpr int Hh  = 512;

// Scratch for x_proj = x @ I^T : [B*T, H] fp32 (128 MB)
__device__ float g_xproj[(size_t)Bb * Tt * Hh];

// ---------------- packed-f32x2 helpers (FFMA2 path, 2x fp32 rate) ----------
#define PACK2(d, lo, hi)   asm("mov.b64 %0, {%1, %2};" : "=l"(d) : "f"(lo), "f"(hi))
#define UNPACK2(lo, hi, s) asm("mov.b64 {%0, %1}, %2;" : "=f"(lo), "=f"(hi) : "l"(s))
#define FMA2(d, a, b)      asm("fma.rn.f32x2 %0, %1, %2, %0;" : "+l"(d) : "l"(a), "l"(b))

// =====================================================================
// Kernel 1: x_proj[m][h] = sum_d x[m][d] * I[h][d]   (NT GEMM, K=128)
// 128x128x32 tiles, 8x8 microtile per thread, FFMA2 inner product.
// =====================================================================
constexpr int BM = 128, BN = 128, BK = 32;

__global__ __launch_bounds__(256, 2) void proj_kernel(const float* __restrict__ X,
                                                      const float* __restrict__ Iw) {
    __shared__ float As[BK][BM + 4];
    __shared__ float Bs[BK][BN + 4];
    const int tid = threadIdx.x;
    const int tx  = tid & 15;   // N microtile index
    const int ty  = tid >> 4;   // M microtile index
    const long long m0 = (long long)blockIdx.y * BM;
    const int       n0 = blockIdx.x * BN;

    unsigned long long acc[8][4];
#pragma unroll
    for (int i = 0; i < 8; i++)
#pragma unroll
        for (int j = 0; j < 4; j++) acc[i][j] = 0ull;

    for (int kt = 0; kt < DIN; kt += BK) {
        // Cooperative load, stored K-major (transposed) into smem
#pragma unroll
        for (int q = 0; q < 4; q++) {
            int p   = tid + q * 256;   // 0..1023 float4 slots
            int row = p >> 3;          // 0..127
            int kq  = p & 7;           // 0..7 (k quad)
            float4 av = *(const float4*)(X + (m0 + row) * DIN + kt + kq * 4);
            As[kq * 4 + 0][row] = av.x; As[kq * 4 + 1][row] = av.y;
            As[kq * 4 + 2][row] = av.z; As[kq * 4 + 3][row] = av.w;
            float4 bv = *(const float4*)(Iw + (long long)(n0 + row) * DIN + kt + kq * 4);
            Bs[kq * 4 + 0][row] = bv.x; Bs[kq * 4 + 1][row] = bv.y;
            Bs[kq * 4 + 2][row] = bv.z; Bs[kq * 4 + 3][row] = bv.w;
        }
        __syncthreads();

#pragma unroll
        for (int k = 0; k < BK; k++) {
            float4 a0 = *(const float4*)&As[k][ty * 8];
            float4 a1 = *(const float4*)&As[k][ty * 8 + 4];
            const unsigned long long* bp =
                (const unsigned long long*)&Bs[k][tx * 8];
            unsigned long long pb0 = bp[0], pb1 = bp[1], pb2 = bp[2], pb3 = bp[3];
            float av[8] = {a0.x, a0.y, a0.z, a0.w, a1.x, a1.y, a1.z, a1.w};
#pragma unroll
            for (int i = 0; i < 8; i++) {
                unsigned long long pa;
                PACK2(pa, av[i], av[i]);
                FMA2(acc[i][0], pa, pb0);
                FMA2(acc[i][1], pa, pb1);
                FMA2(acc[i][2], pa, pb2);
                FMA2(acc[i][3], pa, pb3);
            }
        }
        __syncthreads();
    }

#pragma unroll
    for (int i = 0; i < 8; i++) {
        float4 o0, o1;
        UNPACK2(o0.x, o0.y, acc[i][0]);
        UNPACK2(o0.z, o0.w, acc[i][1]);
        UNPACK2(o1.x, o1.y, acc[i][2]);
        UNPACK2(o1.z, o1.w, acc[i][3]);
        long long row = m0 + ty * 8 + i;
        float* op = g_xproj + row * Hh + n0 + tx * 8;
        *(float4*)op       = o0;
        *(float4*)(op + 4) = o1;
    }
}

// =====================================================================
// Kernel 2: sequential scan. One block per batch, 128 threads, 4 h each.
// J = m n^T is rank-2: tanh(h) @ J^T = (tanh(h)@n) @ m^T -> per step only
// two scalars cross threads.
//  - 4-deep register ring prefetch of x_proj (hides DRAM latency)
//  - fixed-point warp reduce: f32 -> s32 (x2^23), REDUX.SUM, int smem
//    exchange, single I2F at the end (redux.f32 doesn't exist on sm_103)
//  - alpha folded into constants; alpha*xp computed while redux in flight
// =====================================================================
__device__ __forceinline__ float tanh_fast(float x) {
    float y;
    asm("tanh.approx.f32 %0, %1;" : "=f"(y) : "f"(x));
    return y;
}

constexpr float FXSCALE   = 8388608.0f;       // 2^23
constexpr float FXINV     = 1.0f / 8388608.0f;

__global__ __launch_bounds__(128, 1) void scan_kernel(const float* __restrict__ mw,
                                                      const float* __restrict__ nw,
                                                      float* __restrict__ out) {
    const int b    = blockIdx.x;
    const int tid  = threadIdx.x;
    const int wid  = tid >> 5;
    const int lane = tid & 31;

    __shared__ int4 wsum[2][2];  // [double buffer][8 ints: 4 warps x (s0,s1)]

    float h0v = 0.f, h1v = 0.f, h2v = 0.f, h3v = 0.f;
    const int i0 = tid * 4;
    float am0[4], am1[4], n0[4], n1[4];
#pragma unroll
    for (int j = 0; j < 4; j++) {
        am0[j] = (ALPHA_F * FXINV) * mw[(i0 + j) * 2 + 0];  // fold fx descale in
        am1[j] = (ALPHA_F * FXINV) * mw[(i0 + j) * 2 + 1];
        n0[j]  = FXSCALE * nw[(i0 + j) * 2 + 0];            // fold fx scale in
        n1[j]  = FXSCALE * nw[(i0 + j) * 2 + 1];
    }
    const float4* xp4  = (const float4*)(g_xproj + (size_t)b * Tt * Hh);
    float*        outb = out + (size_t)b * Tt * Hh;

    // 4-deep prefetch ring: load for step t+4 is issued at step t.
    float4 ring[4];
#pragma unroll
    for (int j = 0; j < 4; j++) ring[j] = xp4[(size_t)j * (Hh / 4) + tid];

#pragma unroll 4
    for (int t = 0; t < Tt; t++) {
        const int slot = t & 3;
        float4 xp = ring[slot];
        {   // issue prefetch for t+4 (clamped; surplus loads are never consumed)
            int tp = t + 4 < Tt ? t + 4 : Tt - 1;
            ring[slot] = xp4[(size_t)tp * (Hh / 4) + tid];
        }

        // -- critical path: tanh -> local dot (pre-scaled) -> f2i -> REDUX --
        float th0 = tanh_fast(h0v), th1 = tanh_fast(h1v);
        float th2 = tanh_fast(h2v), th3 = tanh_fast(h3v);
        float s0f = fmaf(th0, n0[0], fmaf(th1, n0[1], fmaf(th2, n0[2], th3 * n0[3])));
        float s1f = fmaf(th0, n1[0], fmaf(th1, n1[1], fmaf(th2, n1[2], th3 * n1[3])));
        int s0 = __reduce_add_sync(0xffffffffu, __float2int_rn(s0f));
        int s1 = __reduce_add_sync(0xffffffffu, __float2int_rn(s1f));

        // off-critical-path while redux is in flight
        float ax = ALPHA_F * xp.x, ay = ALPHA_F * xp.y;
        float az = ALPHA_F * xp.z, aw = ALPHA_F * xp.w;

        const int buf = t & 1;
        if (lane == 0) {
            int* w = (int*)&wsum[buf][0];
            w[wid * 2 + 0] = s0;
            w[wid * 2 + 1] = s1;
        }
        __syncthreads();
        int4 p0 = wsum[buf][0];
        int4 p1 = wsum[buf][1];
        float S0 = (float)((p0.x + p0.z) + (p1.x + p1.z));  // still x2^23
        float S1 = (float)((p0.y + p0.w) + (p1.y + p1.w));

        // h = (1-a)h + a*xp + (a*m0/2^23)S0 + (a*m1/2^23)S1
        h0v = fmaf(h0v, 1.0f - ALPHA_F, fmaf(am0[0], S0, fmaf(am1[0], S1, ax)));
        h1v = fmaf(h1v, 1.0f - ALPHA_F, fmaf(am0[1], S0, fmaf(am1[1], S1, ay)));
        h2v = fmaf(h2v, 1.0f - ALPHA_F, fmaf(am0[2], S0, fmaf(am1[2], S1, az)));
        h3v = fmaf(h3v, 1.0f - ALPHA_F, fmaf(am0[3], S0, fmaf(am1[3], S1, aw)));

        *(float4*)&outb[(size_t)t * Hh + i0] = make_float4(h0v, h1v, h2v, h3v);
    }
}

// =====================================================================
extern "C" void kernel_launch(void* const* d_in, const int* in_sizes, int n_in,
                              void* d_out, int out_size) {
    const float* x  = (const float*)d_in[0];  // [32, 2048, 128]
    const float* m  = (const float*)d_in[1];  // [512, 2]
    const float* n  = (const float*)d_in[2];  // [512, 2]
    const float* Iw = (const float*)d_in[3];  // [512, 128]
    float* out = (float*)d_out;               // [32, 2048, 512]

    dim3 pg(Hh / BN, (Bb * Tt) / BM);  // (4, 512)
    proj_kernel<<<pg, 256>>>(x, Iw);
    scan_kernel<<<Bb, 128>>>(m, n, out);
}